// round 5
// baseline (speedup 1.0000x reference)
#include <cuda_runtime.h>

// out[b, oz, oy, ox] = in[b*3137*768 + (1 + n*196 + g1*14 + g2)*768 + ch]
//   z = floor(oz*9/4)  -> n = oz>>2, c0 = z - 9n   (c0 in {0,2,4,6})
//   y = floor(oy*63/32) -> g1 = y/9, c1 = y%9
//   x = floor(ox*63/32) -> g2 = x/9, c2 = x%9
//   ch = floor(float32(c0*81 + c1*9 + c2) * float32(768.0/729.0))  (bit-exact JAX)
//
// Per oz only ONE contiguous 86-float channel band per token is touched.
// CTA = (b, oz, oy-half): warp-per-token coalesced band load into smem
// (no divisions), then 64x32 output tile via smem gathers + coalesced stores.

__global__ __launch_bounds__(256)
void FRAMES_VisionTransformer_28166395527587_kernel(const float* __restrict__ in,
                                                    float* __restrict__ out) {
    __shared__ float s[98 * 88];          // 34,496 B -> 6 CTAs/SM

    const unsigned bid = blockIdx.x;      // 64 b * 64 oz * 2 halves = 8192
    const unsigned h  = bid & 1u;         // oy in [32h, 32h+32)
    const unsigned oz = (bid >> 1) & 63u;
    const unsigned b  = bid >> 7;
    const unsigned tid  = threadIdx.x;
    const unsigned warp = tid >> 5;
    const unsigned lane = tid & 31u;

    const unsigned z  = (oz * 9u) >> 2;   // floor(oz*2.25), exact
    const unsigned n  = oz >> 2;          // z/9
    const unsigned c0 = z - n * 9u;       // {0,2,4,6}

    const float SC = (float)(768.0 / 729.0);   // correctly-rounded fp32
    const int lo = __float2int_rd((float)(c0 * 81u) * SC);

    // ---- stage 1: 98 token bands of 86 floats, warp-per-token, coalesced.
    const float* base = in + (size_t)b * (3137u * 768u)
                           + (size_t)(1u + n * 196u + 98u * h) * 768u
                           + (size_t)lo;
    #pragma unroll
    for (unsigned i = 0; i < 13; ++i) {
        unsigned tok = warp + 8u * i;          // 0..97 (+ stragglers masked)
        if (tok < 98u) {
            const float* src = base + (size_t)tok * 768u;
            float* dst = &s[tok * 88u];
            dst[lane]       = __ldcs(&src[lane]);
            dst[lane + 32u] = __ldcs(&src[lane + 32u]);
            if (lane < 22u)
                dst[lane + 64u] = __ldcs(&src[lane + 64u]);
        }
    }
    __syncthreads();

    // ---- stage 2: 64x32 output tile
    const unsigned ox = tid & 63u;
    const unsigned x  = (ox * 63u) >> 5;            // floor(ox*1.96875), exact
    const unsigned g2 = x / 9u;
    const unsigned c2 = x - g2 * 9u;
    const unsigned oy_base = 32u * h + (tid >> 6);  // + 4k, k=0..7

    const unsigned cb = c0 * 81u + c2;
    size_t out_base = (((size_t)b * 64u + oz) * 64u + oy_base) * 64u + ox;

    #pragma unroll
    for (int k = 0; k < 8; ++k) {
        unsigned oy = oy_base + 4u * (unsigned)k;
        unsigned y  = (oy * 63u) >> 5;              // floor(oy*1.96875), exact
        unsigned g1 = y / 9u;
        unsigned c1 = y - g1 * 9u;
        unsigned tl = (g1 - 7u * h) * 14u + g2;     // local token 0..97
        int ch = __float2int_rd((float)(cb + c1 * 9u) * SC);   // bit-exact
        float v = s[tl * 88u + (unsigned)(ch - lo)];
        __stcs(&out[out_base + (size_t)(4 * k) * 64u], v);
    }
}

extern "C" void kernel_launch(void* const* d_in, const int* in_sizes, int n_in,
                              void* d_out, int out_size) {
    const float* in = (const float*)d_in[0];
    float* out = (float*)d_out;
    FRAMES_VisionTransformer_28166395527587_kernel<<<8192, 256>>>(in, out);
}

// round 6
// speedup vs baseline: 1.3508x; 1.3508x over previous
#include <cuda_runtime.h>

// out[b, oz, oy, ox] = in[b*3137*768 + (1 + n*196 + g1*14 + g2)*768 + ch]
//   z = floor(oz*9/4)   -> n = z/9, c0 = z%9
//   y = floor(oy*63/32) -> g1 = y/9, c1 = y%9
//   x = floor(ox*63/32) -> g2 = x/9, c2 = x%9
//   ch = floor(float32(c0*81 + c1*9 + c2) * float32(768.0/729.0))  (bit-exact JAX)
//
// Minimal-traffic direct gather (proven vs smem staging in R3/R5).
// Warp = 32 consecutive ox -> gather clusters into ~7 tokens x ~2 sectors.
// Thread = 4 oy values (stride 16); 4 coalesced scalar streaming stores.
// __ldcg: L2-only reads (no L1 fill; gather has ~0% L1 reuse).
// __launch_bounds__(256,8): pin 2048 resident threads/SM for max MLP.

__global__ __launch_bounds__(256, 8)
void FRAMES_VisionTransformer_28166395527587_kernel(const float* __restrict__ in,
                                                    float* __restrict__ out) {
    unsigned t = blockIdx.x * blockDim.x + threadIdx.x;   // 2^22 threads
    unsigned ox  = t & 63u;
    unsigned oy0 = (t >> 6) & 15u;       // thread covers oy0 + 16k, k=0..3
    unsigned oz  = (t >> 10) & 63u;
    unsigned b   = t >> 16;

    // Exact integer forms of the fp32 nearest-index maps (exact in fp32)
    unsigned z = (oz * 9u) >> 2;                       // floor(oz*2.25)
    unsigned n  = z / 9u;   unsigned c0 = z - n * 9u;
    unsigned x = (ox * 63u) >> 5;                      // floor(ox*1.96875)
    unsigned g2 = x / 9u;   unsigned c2 = x - g2 * 9u;

    const size_t row_base = (size_t)b * (3137u * 768u)
                          + (size_t)(1u + n * 196u + g2) * 768u;
    const unsigned cbase = c0 * 81u + c2;

    // float32(768.0/729.0): correctly-rounded; fp32 mul + floor matches JAX bit-exactly
    const float SC = (float)(768.0 / 729.0);

    float v[4];
    #pragma unroll
    for (int k = 0; k < 4; ++k) {
        unsigned oy = oy0 + 16u * (unsigned)k;
        unsigned y  = (oy * 63u) >> 5;                 // floor(oy*1.96875)
        unsigned g1 = y / 9u;  unsigned c1 = y - g1 * 9u;
        unsigned ch = (unsigned)__float2int_rd((float)(cbase + c1 * 9u) * SC);
        v[k] = __ldcg(&in[row_base + (size_t)(g1 * 14u) * 768u + ch]);
    }

    size_t out_base = (((size_t)b * 64u + oz) * 64u + oy0) * 64u + ox;
    #pragma unroll
    for (int k = 0; k < 4; ++k)
        __stcs(&out[out_base + (size_t)k * (16u * 64u)], v[k]);
}

extern "C" void kernel_launch(void* const* d_in, const int* in_sizes, int n_in,
                              void* d_out, int out_size) {
    const float* in = (const float*)d_in[0];
    float* out = (float*)d_out;
    const unsigned n_threads = 16777216u / 4u;    // 4,194,304 (4 outputs/thread)
    const unsigned block = 256u;
    const unsigned grid = n_threads / block;      // 16,384
    FRAMES_VisionTransformer_28166395527587_kernel<<<grid, block>>>(in, out);
}